// round 5
// baseline (speedup 1.0000x reference)
#include <cuda_runtime.h>
#include <cuda_bf16.h>

// ShadingCompositor: P=100000, N=8, H=W=256, K=8
#define PMAX 100000

// Precomputed per-point Phong color {r,g,b,0}, 16B aligned -> 1 sector per gather
__device__ __align__(128) float4 g_colors[PMAX];

__device__ __forceinline__ float pow_uint(float a, int e) {
    float r = 1.0f, b = a;
    int n = e;
    while (n) {
        if (n & 1) r *= b;
        b *= b;
        n >>= 1;
    }
    return r;
}

__global__ void precompute_colors(const float* __restrict__ pts,
                                  const float* __restrict__ nrm,
                                  const float* __restrict__ lloc,
                                  const float* __restrict__ lamb,
                                  const float* __restrict__ ldif,
                                  const float* __restrict__ lspc,
                                  const float* __restrict__ mamb,
                                  const float* __restrict__ mdif,
                                  const float* __restrict__ mspc,
                                  const float* __restrict__ cam,
                                  const int*   __restrict__ shin,
                                  int P) {
    int i = blockIdx.x * blockDim.x + threadIdx.x;
    if (i >= P) return;

    float Lx = lloc[0], Ly = lloc[1], Lz = lloc[2];
    float Cx = cam[0],  Cy = cam[1],  Cz = cam[2];
    float ax = lamb[0] * mamb[0], ay = lamb[1] * mamb[1], az = lamb[2] * mamb[2];
    float dx = ldif[0] * mdif[0], dy = ldif[1] * mdif[1], dz = ldif[2] * mdif[2];
    float sx = lspc[0] * mspc[0], sy = lspc[1] * mspc[1], sz = lspc[2] * mspc[2];
    int raw = shin[0];
    int expn = (raw > 0 && raw < (1 << 20)) ? raw : (int)__int_as_float(raw);

    float px = pts[3 * i], py = pts[3 * i + 1], pz = pts[3 * i + 2];
    float nx = nrm[3 * i], ny = nrm[3 * i + 1], nz = nrm[3 * i + 2];

    // light direction
    float lvx = Lx - px, lvy = Ly - py, lvz = Lz - pz;
    float ln = sqrtf(lvx * lvx + lvy * lvy + lvz * lvz);
    float ls = 1.0f / fmaxf(ln, 1e-6f);
    float dlx = lvx * ls, dly = lvy * ls, dlz = lvz * ls;

    float cosang = nx * dlx + ny * dly + nz * dlz;

    // view direction
    float vvx = Cx - px, vvy = Cy - py, vvz = Cz - pz;
    float vn = sqrtf(vvx * vvx + vvy * vvy + vvz * vvz);
    float vs = 1.0f / fmaxf(vn, 1e-6f);
    float vwx = vvx * vs, vwy = vvy * vs, vwz = vvz * vs;

    // reflect = 2*cos*n - dirL
    float c2 = 2.0f * cosang;
    float rx = c2 * nx - dlx, ry = c2 * ny - dly, rz = c2 * nz - dlz;

    float alpha = vwx * rx + vwy * ry + vwz * rz;
    alpha = fmaxf(alpha, 0.0f);
    alpha = (cosang > 0.0f) ? alpha : 0.0f;
    float spec = pow_uint(alpha, expn);

    float relc = fmaxf(cosang, 0.0f);

    g_colors[i] = make_float4(ax + dx * relc + sx * spec,
                              ay + dy * relc + sy * spec,
                              az + dz * relc + sz * spec, 0.f);
}

// Force 2048 threads/SM (8 blocks x 256) -> ptxas targets 32 regs -> ~100% occ.
__global__ __launch_bounds__(256, 8)
void shade_kernel(const int4* __restrict__ idxv,
                  const float4* __restrict__ dstv,
                  float* __restrict__ out,
                  int npix) {
    int pix = blockIdx.x * blockDim.x + threadIdx.x;
    if (pix >= npix) return;

    float4 q0 = dstv[pix * 2];
    float4 q1 = dstv[pix * 2 + 1];
    int4 i0 = idxv[pix * 2];
    int4 i1 = idxv[pix * 2 + 1];

    // ---- weights first: ds[] dies before the gather window ----
    float w[8] = { q0.x, q0.y, q0.z, q0.w, q1.x, q1.y, q1.z, q1.w };
    float wsum = 0.f;
#pragma unroll
    for (int k = 0; k < 8; k++) {
        float d = w[k];
        d = (d != -1.0f) ? d : 0.0f;
        w[k] = d;
        wsum += fabsf(d);
    }
    float winv = 1.0f / fmaxf(wsum, 1e-12f);
#pragma unroll
    for (int k = 0; k < 8; k++) w[k] *= winv;

    int ids[8] = { i0.x, i0.y, i0.z, i0.w, i1.x, i1.y, i1.z, i1.w };

    // ---- gathers + weighted accumulation; ptxas staggers under 32-reg budget ----
    float4 col[8];
#pragma unroll
    for (int k = 0; k < 8; k++) {
        int j = ids[k];
        j = (j < 0) ? 0 : j;
        col[k] = g_colors[j];
    }

    float accx = 0.f, accy = 0.f, accz = 0.f;
#pragma unroll
    for (int k = 0; k < 8; k++) {
        accx += w[k] * col[k].x;
        accy += w[k] * col[k].y;
        accz += w[k] * col[k].z;
    }

    out[3 * pix]     = accx;
    out[3 * pix + 1] = accy;
    out[3 * pix + 2] = accz;
}

extern "C" void kernel_launch(void* const* d_in, const int* in_sizes, int n_in,
                              void* d_out, int out_size) {
    const int*   idx    = (const int*)d_in[0];
    const float* dists  = (const float*)d_in[1];
    const float* points = (const float*)d_in[2];
    const float* normals= (const float*)d_in[3];
    const float* lloc   = (const float*)d_in[4];
    const float* lamb   = (const float*)d_in[5];
    const float* ldif   = (const float*)d_in[6];
    const float* lspc   = (const float*)d_in[7];
    const float* mamb   = (const float*)d_in[8];
    const float* mdif   = (const float*)d_in[9];
    const float* mspc   = (const float*)d_in[10];
    const float* cam    = (const float*)d_in[11];
    const int*   shin   = (const int*)d_in[12];

    int P = in_sizes[2] / 3;
    if (P > PMAX) P = PMAX;
    int npix = in_sizes[0] / 8;   // K = 8

    precompute_colors<<<(P + 255) / 256, 256>>>(
        points, normals, lloc, lamb, ldif, lspc, mamb, mdif, mspc, cam, shin, P);

    shade_kernel<<<(npix + 255) / 256, 256>>>(
        (const int4*)idx, (const float4*)dists, (float*)d_out, npix);
}

// round 7
// speedup vs baseline: 1.0299x; 1.0299x over previous
#include <cuda_runtime.h>
#include <cuda_bf16.h>
#include <cuda_fp16.h>

// ShadingCompositor: P=100000, N=8, H=W=256, K=8
#define PMAX 100000

// Precomputed per-point Phong color packed as 4x fp16 {r,g,b,0} = 8 bytes.
// Table = 800KB -> per-SM hot set fits L1 (228KB) once streaming uses .cs.
__device__ __align__(128) uint2 g_colors8[PMAX];

__device__ __forceinline__ float pow_uint(float a, int e) {
    float r = 1.0f, b = a;
    int n = e;
    while (n) {
        if (n & 1) r *= b;
        b *= b;
        n >>= 1;
    }
    return r;
}

__global__ void precompute_colors(const float* __restrict__ pts,
                                  const float* __restrict__ nrm,
                                  const float* __restrict__ lloc,
                                  const float* __restrict__ lamb,
                                  const float* __restrict__ ldif,
                                  const float* __restrict__ lspc,
                                  const float* __restrict__ mamb,
                                  const float* __restrict__ mdif,
                                  const float* __restrict__ mspc,
                                  const float* __restrict__ cam,
                                  const int*   __restrict__ shin,
                                  int P) {
    int i = blockIdx.x * blockDim.x + threadIdx.x;
    if (i >= P) return;

    float Lx = lloc[0], Ly = lloc[1], Lz = lloc[2];
    float Cx = cam[0],  Cy = cam[1],  Cz = cam[2];
    float ax = lamb[0] * mamb[0], ay = lamb[1] * mamb[1], az = lamb[2] * mamb[2];
    float dx = ldif[0] * mdif[0], dy = ldif[1] * mdif[1], dz = ldif[2] * mdif[2];
    float sx = lspc[0] * mspc[0], sy = lspc[1] * mspc[1], sz = lspc[2] * mspc[2];
    int raw = shin[0];
    int expn = (raw > 0 && raw < (1 << 20)) ? raw : (int)__int_as_float(raw);

    float px = pts[3 * i], py = pts[3 * i + 1], pz = pts[3 * i + 2];
    float nx = nrm[3 * i], ny = nrm[3 * i + 1], nz = nrm[3 * i + 2];

    // light direction
    float lvx = Lx - px, lvy = Ly - py, lvz = Lz - pz;
    float ln = sqrtf(lvx * lvx + lvy * lvy + lvz * lvz);
    float ls = 1.0f / fmaxf(ln, 1e-6f);
    float dlx = lvx * ls, dly = lvy * ls, dlz = lvz * ls;

    float cosang = nx * dlx + ny * dly + nz * dlz;

    // view direction
    float vvx = Cx - px, vvy = Cy - py, vvz = Cz - pz;
    float vn = sqrtf(vvx * vvx + vvy * vvy + vvz * vvz);
    float vs = 1.0f / fmaxf(vn, 1e-6f);
    float vwx = vvx * vs, vwy = vvy * vs, vwz = vvz * vs;

    // reflect = 2*cos*n - dirL
    float c2 = 2.0f * cosang;
    float rx = c2 * nx - dlx, ry = c2 * ny - dly, rz = c2 * nz - dlz;

    float alpha = vwx * rx + vwy * ry + vwz * rz;
    alpha = fmaxf(alpha, 0.0f);
    alpha = (cosang > 0.0f) ? alpha : 0.0f;
    float spec = pow_uint(alpha, expn);

    float relc = fmaxf(cosang, 0.0f);

    float cr = ax + dx * relc + sx * spec;
    float cg = ay + dy * relc + sy * spec;
    float cb = az + dz * relc + sz * spec;

    __half2 rg = __floats2half2_rn(cr, cg);
    __half2 b0 = __floats2half2_rn(cb, 0.f);
    uint2 packed;
    packed.x = *reinterpret_cast<unsigned int*>(&rg);
    packed.y = *reinterpret_cast<unsigned int*>(&b0);
    g_colors8[i] = packed;
}

__global__ __launch_bounds__(256, 8)
void shade_kernel(const int4* __restrict__ idxv,
                  const float4* __restrict__ dstv,
                  float* __restrict__ out,
                  int npix) {
    int pix = blockIdx.x * blockDim.x + threadIdx.x;
    if (pix >= npix) return;

    // Streaming inputs: evict-first so they don't thrash the L1-resident table
    float4 q0 = __ldcs(&dstv[pix * 2]);
    float4 q1 = __ldcs(&dstv[pix * 2 + 1]);
    int4 i0 = __ldcs(&idxv[pix * 2]);
    int4 i1 = __ldcs(&idxv[pix * 2 + 1]);

    // ---- weights first (die before gather window) ----
    float w[8] = { q0.x, q0.y, q0.z, q0.w, q1.x, q1.y, q1.z, q1.w };
    float wsum = 0.f;
#pragma unroll
    for (int k = 0; k < 8; k++) {
        float d = w[k];
        d = (d != -1.0f) ? d : 0.0f;
        w[k] = d;
        wsum += fabsf(d);
    }
    float winv = 1.0f / fmaxf(wsum, 1e-12f);
#pragma unroll
    for (int k = 0; k < 8; k++) w[k] *= winv;

    int ids[8] = { i0.x, i0.y, i0.z, i0.w, i1.x, i1.y, i1.z, i1.w };

    // ---- 8 independent 8B gathers (read-only path, L1-cached) ----
    uint2 col[8];
#pragma unroll
    for (int k = 0; k < 8; k++) {
        int j = ids[k];
        j = (j < 0) ? 0 : j;
        col[k] = __ldg(&g_colors8[j]);
    }

    float accx = 0.f, accy = 0.f, accz = 0.f;
#pragma unroll
    for (int k = 0; k < 8; k++) {
        __half2 rg = *reinterpret_cast<__half2*>(&col[k].x);
        __half2 b0 = *reinterpret_cast<__half2*>(&col[k].y);
        float2 frg = __half22float2(rg);
        float fb = __low2float(b0);
        accx += w[k] * frg.x;
        accy += w[k] * frg.y;
        accz += w[k] * fb;
    }

    // Streaming output: evict-first
    __stcs(&out[3 * pix],     accx);
    __stcs(&out[3 * pix + 1], accy);
    __stcs(&out[3 * pix + 2], accz);
}

extern "C" void kernel_launch(void* const* d_in, const int* in_sizes, int n_in,
                              void* d_out, int out_size) {
    const int*   idx    = (const int*)d_in[0];
    const float* dists  = (const float*)d_in[1];
    const float* points = (const float*)d_in[2];
    const float* normals= (const float*)d_in[3];
    const float* lloc   = (const float*)d_in[4];
    const float* lamb   = (const float*)d_in[5];
    const float* ldif   = (const float*)d_in[6];
    const float* lspc   = (const float*)d_in[7];
    const float* mamb   = (const float*)d_in[8];
    const float* mdif   = (const float*)d_in[9];
    const float* mspc   = (const float*)d_in[10];
    const float* cam    = (const float*)d_in[11];
    const int*   shin   = (const int*)d_in[12];

    int P = in_sizes[2] / 3;
    if (P > PMAX) P = PMAX;
    int npix = in_sizes[0] / 8;   // K = 8

    precompute_colors<<<(P + 255) / 256, 256>>>(
        points, normals, lloc, lamb, ldif, lspc, mamb, mdif, mspc, cam, shin, P);

    shade_kernel<<<(npix + 255) / 256, 256>>>(
        (const int4*)idx, (const float4*)dists, (float*)d_out, npix);
}